// round 7
// baseline (speedup 1.0000x reference)
#include <cuda_runtime.h>
#include <cstdint>
#include <math.h>

// Problem constants
#define HIN 256
#define WIN 256
#define CIN 16
#define COUT 64
#define OH 254
#define OW 254
#define KDIM 144          // CIN * 3 * 3
#define PROWS 10          // patch rows  (8 out rows + 2)
#define PCOLS 18          // patch cols  (16 out cols + 2)
#define PW 19             // patch row stride (floats) — padded
#define BST 148           // weight smem k-stride (148 mod 32 = 20 -> conflict-free frags)

// SMEM layout (in 4-byte words)
#define S_PATCH 0                        // 16*10*19 = 3040
#define S_B     (S_PATCH + CIN*PROWS*PW) // 64*148  = 9472
#define S_KOFF  (S_B + COUT*BST)         // 144
#define S_BIAS  (S_KOFF + KDIM)          // 64
#define S_MIN   (S_BIAS + COUT)          // 128
#define S_TOTAL (S_MIN + 128)            // words

__device__ __forceinline__ uint32_t f2tf32(float f) {
    uint32_t u;
    asm("cvt.rna.tf32.f32 %0, %1;" : "=r"(u) : "f"(f));
    return u;
}

__global__ __launch_bounds__(256)
void conv_min_tanh_kernel(const float* __restrict__ x,
                          const float* __restrict__ w,
                          const float* __restrict__ bias,
                          float* __restrict__ out) {
    extern __shared__ uint32_t smem[];
    uint32_t* Ps     = smem + S_PATCH;
    uint32_t* Bsm    = smem + S_B;
    int*      koff   = (int*)  (smem + S_KOFF);
    float*    bsh    = (float*)(smem + S_BIAS);
    float*    minbuf = (float*)(smem + S_MIN);

    const int tid = threadIdx.x;
    const int b   = blockIdx.z;
    const int y0  = blockIdx.y * 8;    // output-row origin of this tile
    const int x0  = blockIdx.x * 16;   // output-col origin of this tile

    // ---- stage input patch (fp32 -> tf32), zero-fill out-of-bounds ----
    const float* xb = x + (size_t)b * CIN * HIN * WIN;
    for (int i = tid; i < CIN * PROWS * PCOLS; i += 256) {
        int cin = i / (PROWS * PCOLS);
        int r   = i - cin * (PROWS * PCOLS);
        int yy  = r / PCOLS;
        int xx  = r - yy * PCOLS;
        int gy = y0 + yy, gx = x0 + xx;
        float v = 0.0f;
        if (gy < HIN && gx < WIN)
            v = xb[(cin * HIN + gy) * WIN + gx];
        Ps[cin * (PROWS * PW) + yy * PW + xx] = f2tf32(v);
    }
    // ---- stage weights: w is [Cout][Cin*3*3] = [64][144], k-major already ----
    for (int i = tid; i < COUT * KDIM; i += 256) {
        int n = i / KDIM, k = i - n * KDIM;
        Bsm[n * BST + k] = f2tf32(w[i]);
    }
    // ---- koff table: k -> offset within the patch for (cin, kh, kw) ----
    if (tid < KDIM) {
        int cin = tid / 9, r = tid % 9;
        int kh = r / 3, kw = r - kh * 3;
        koff[tid] = (cin * PROWS + kh) * PW + kw;
    }
    if (tid < COUT) bsh[tid] = bias[tid];
    __syncthreads();

    // ---- warp/thread mapping ----
    const int lane = tid & 31;
    const int warp = tid >> 5;
    const int wm   = warp & 3;   // 4 warps across M (32 pixels each)
    const int wn   = warp >> 2;  // 2 warps across N (32 couts each)
    const int g    = lane >> 2;  // 0..7
    const int tig  = lane & 3;   // 0..3
    const int nbase = wn * 32;
    const int py0   = wm * 2;    // pixel row of mtile 0 (each m16 tile = one 16-wide pixel row)

    float acc[2][4][4];
    #pragma unroll
    for (int mt = 0; mt < 2; mt++)
        #pragma unroll
        for (int nt = 0; nt < 4; nt++)
            #pragma unroll
            for (int r = 0; r < 4; r++) acc[mt][nt][r] = 0.0f;

    // ---- mainloop: K = 144 in 18 steps of k8 ----
    #pragma unroll 2
    for (int ks = 0; ks < 18; ks++) {
        const int kb = ks * 8;
        const int o1 = koff[kb + tig];
        const int o2 = koff[kb + tig + 4];

        uint32_t A[2][4];
        #pragma unroll
        for (int mt = 0; mt < 2; mt++) {
            const int pb = (py0 + mt) * PW;
            A[mt][0] = Ps[o1 + pb + g];       // row g,   col tig
            A[mt][1] = Ps[o1 + pb + g + 8];   // row g+8, col tig
            A[mt][2] = Ps[o2 + pb + g];       // row g,   col tig+4
            A[mt][3] = Ps[o2 + pb + g + 8];   // row g+8, col tig+4
        }
        uint32_t Bf[4][2];
        #pragma unroll
        for (int nt = 0; nt < 4; nt++) {
            const int nb = (nbase + nt * 8 + g) * BST + kb;
            Bf[nt][0] = Bsm[nb + tig];        // k = tig,   n = g
            Bf[nt][1] = Bsm[nb + tig + 4];    // k = tig+4, n = g
        }
        #pragma unroll
        for (int mt = 0; mt < 2; mt++)
            #pragma unroll
            for (int nt = 0; nt < 4; nt++) {
                asm volatile(
                    "mma.sync.aligned.m16n8k8.row.col.f32.tf32.tf32.f32 "
                    "{%0,%1,%2,%3}, {%4,%5,%6,%7}, {%8,%9}, {%0,%1,%2,%3};"
                    : "+f"(acc[mt][nt][0]), "+f"(acc[mt][nt][1]),
                      "+f"(acc[mt][nt][2]), "+f"(acc[mt][nt][3])
                    : "r"(A[mt][0]), "r"(A[mt][1]), "r"(A[mt][2]), "r"(A[mt][3]),
                      "r"(Bf[nt][0]), "r"(Bf[nt][1]));
            }
    }

    // ---- epilogue: +bias, min over the warp's 32 couts (regs + shfl) ----
    // c0:(row g, col 2t) c1:(g,2t+1) c2:(g+8,2t) c3:(g+8,2t+1)
    float pm[2][2];
    #pragma unroll
    for (int mt = 0; mt < 2; mt++)
        #pragma unroll
        for (int h = 0; h < 2; h++) {
            float v = 3.4e38f;
            #pragma unroll
            for (int nt = 0; nt < 4; nt++) {
                const int n0 = nbase + nt * 8 + 2 * tig;
                v = fminf(v, acc[mt][nt][2 * h]     + bsh[n0]);
                v = fminf(v, acc[mt][nt][2 * h + 1] + bsh[n0 + 1]);
            }
            // reduce across tig (lanes differing in bits 0..1 share the pixel)
            v = fminf(v, __shfl_xor_sync(0xffffffffu, v, 1));
            v = fminf(v, __shfl_xor_sync(0xffffffffu, v, 2));
            pm[mt][h] = v;
        }

    // ---- combine the two warpN halves through smem, then tanh(tanh), store ----
    if (wn == 0 && tig == 0) {
        #pragma unroll
        for (int mt = 0; mt < 2; mt++)
            #pragma unroll
            for (int h = 0; h < 2; h++) {
                const int pix = (py0 + mt) * 16 + g + h * 8;
                minbuf[pix] = pm[mt][h];
            }
    }
    __syncthreads();
    if (wn == 1 && tig == 0) {
        #pragma unroll
        for (int mt = 0; mt < 2; mt++)
            #pragma unroll
            for (int h = 0; h < 2; h++) {
                const int py = py0 + mt;
                const int px = g + h * 8;
                const float m = fminf(pm[mt][h], minbuf[py * 16 + px]);
                const float r = tanhf(tanhf(m));
                const int oy = y0 + py, ox = x0 + px;
                if (oy < OH && ox < OW)
                    out[(size_t)b * (OH * OW) + oy * OW + ox] = r;
            }
    }
}

extern "C" void kernel_launch(void* const* d_in, const int* in_sizes, int n_in,
                              void* d_out, int out_size) {
    const float* x  = (const float*)d_in[0];
    const float* w  = (const float*)d_in[1];
    const float* bi = (const float*)d_in[2];
    float* out = (float*)d_out;

    const int smem_bytes = S_TOTAL * 4;  // 51,392 B > 48K default -> opt-in
    cudaFuncSetAttribute(conv_min_tanh_kernel,
                         cudaFuncAttributeMaxDynamicSharedMemorySize, smem_bytes);

    dim3 grid(16, 32, 64);   // x-tiles(16*16=256>=254), y-tiles(32*8=256>=254), batch
    conv_min_tanh_kernel<<<grid, 256, smem_bytes>>>(x, w, bi, out);
}

// round 10
// speedup vs baseline: 1.8766x; 1.8766x over previous
#include <cuda_runtime.h>
#include <cstdint>
#include <math.h>

// Problem constants
#define HIN 256
#define WIN 256
#define CIN 16
#define COUT 64
#define OH 254
#define OW 254
#define KDIM 144          // CIN * 3 * 3
#define PROWS 18          // patch rows  (16 out rows + 2)
#define PCOLS 18          // patch cols  (16 out cols + 2)
#define PW 19             // patch row stride (words), padded
#define BST 152           // weight k-stride; 152 mod 32 = 24 -> LDS.64 conflict-free

// SMEM layout (4-byte words)
#define S_PATCH 0                         // 16*18*19 = 5472
#define S_B     (S_PATCH + CIN*PROWS*PW)  // 64*152   = 9728
#define S_KOFF  (S_B + COUT*BST)          // 144
#define S_BIAS  (S_KOFF + KDIM)           // 64
#define S_TOTAL (S_BIAS + COUT)           // 15408 words = 61632 B

__device__ float g_wp[COUT * BST];        // pre-permuted tf32 weights (smem-image)

__device__ __forceinline__ uint32_t f2tf32(float f) {
    uint32_t u;
    asm("cvt.rna.tf32.f32 %0, %1;" : "=r"(u) : "f"(f));
    return u;
}

// Permutation within each k8 block: pos(kl) = (kl&3)*2 + (kl>>2)
// -> lane tig reads [k=tig, k=tig+4] as ONE LDS.64 at offset kb + 2*tig.
__global__ void prep_weights(const float* __restrict__ w) {
    int idx = blockIdx.x * blockDim.x + threadIdx.x;
    if (idx < COUT * KDIM) {
        int n = idx / KDIM, k = idx - n * KDIM;
        int kb = k & ~7, kl = k & 7;
        int pos = ((kl & 3) << 1) | (kl >> 2);
        ((uint32_t*)g_wp)[n * BST + kb + pos] = f2tf32(w[idx]);
    }
}

__global__ __launch_bounds__(256, 2)
void conv_min_tanh_kernel(const float* __restrict__ x,
                          const float* __restrict__ bias,
                          float* __restrict__ out) {
    extern __shared__ uint32_t smem[];
    uint32_t*   Ps  = smem + S_PATCH;
    uint32_t*   Bsm = smem + S_B;
    int*        kof = (int*)(smem + S_KOFF);
    float*      bsh = (float*)(smem + S_BIAS);

    const int tid = threadIdx.x;
    const int b   = blockIdx.z;
    const int y0  = blockIdx.y * 16;   // output-row origin (16-row tile)
    const int x0  = blockIdx.x * 16;   // output-col origin

    // ---- stage input patch (fp32 -> tf32), zero-fill OOB ----
    // Each thread owns up to 2 (yy,xx) positions and walks all 16 cin (MLP 16).
    const float* xb = x + (size_t)b * CIN * HIN * WIN;
    #pragma unroll
    for (int p0 = 0; p0 < 2; p0++) {
        int pos = tid + p0 * 256;
        if (pos < PROWS * PCOLS) {
            int yy = pos / PCOLS, xx = pos - yy * PCOLS;
            int gy = y0 + yy, gx = x0 + xx;
            bool inb = (gy < HIN) && (gx < WIN);
            const float* src = xb + gy * WIN + gx;
            uint32_t*    dst = Ps + yy * PW + xx;
            #pragma unroll
            for (int c = 0; c < CIN; c++) {
                float v = inb ? src[c * (HIN * WIN)] : 0.0f;
                dst[c * (PROWS * PW)] = f2tf32(v);
            }
        }
    }
    // ---- stage weights: pure float4 copy of the pre-permuted image ----
    {
        const float4* ws = (const float4*)g_wp;
        float4*       wd = (float4*)Bsm;
        #pragma unroll
        for (int i = tid; i < (COUT * BST) / 4; i += 256)
            wd[i] = ws[i];
    }
    // ---- koff table, same permutation as B (enables LDS.64 pair read) ----
    if (tid < KDIM) {
        int cin = tid / 9, r = tid % 9;
        int kh = r / 3, kw = r - kh * 3;
        int off = (cin * PROWS + kh) * PW + kw;
        int kb = tid & ~7, kl = tid & 7;
        int pos = ((kl & 3) << 1) | (kl >> 2);
        kof[kb + pos] = off;
    }
    if (tid < COUT) bsh[tid] = bias[tid];
    __syncthreads();

    // ---- mapping: 8 warps, each owns 2 pixel rows x 16 cols x ALL 64 couts ----
    const int lane = tid & 31;
    const int warp = tid >> 5;       // 0..7
    const int g    = lane >> 2;      // 0..7
    const int tig  = lane & 3;       // 0..3
    const int rbase = warp * 2;      // warp's first output row within tile

    const uint32_t* Pb0 = Ps + rbase * PW + g;
    const uint32_t* Bb  = Bsm + g * BST + 2 * tig;

    float acc[2][8][4];
    #pragma unroll
    for (int mt = 0; mt < 2; mt++)
        #pragma unroll
        for (int nt = 0; nt < 8; nt++)
            #pragma unroll
            for (int r = 0; r < 4; r++) acc[mt][nt][r] = 0.0f;

    // ---- mainloop: K = 144 in 18 k8 steps ----
    #pragma unroll 2
    for (int ks = 0; ks < 18; ks++) {
        const int kb = ks * 8;
        const int2 kp = *(const int2*)(kof + kb + 2 * tig);  // {koff[k=tig], koff[k=tig+4]}
        const int o1 = kp.x, o2 = kp.y;

        uint32_t A[2][4];
        #pragma unroll
        for (int mt = 0; mt < 2; mt++) {
            const uint32_t* p = Pb0 + mt * PW;
            A[mt][0] = p[o1];        // row g,   k=tig
            A[mt][1] = p[o1 + 8];    // row g+8, k=tig
            A[mt][2] = p[o2];        // row g,   k=tig+4
            A[mt][3] = p[o2 + 8];    // row g+8, k=tig+4
        }
        uint2 Bf[8];
        #pragma unroll
        for (int nt = 0; nt < 8; nt++)
            Bf[nt] = *(const uint2*)(Bb + nt * 8 * BST + kb);  // {k=tig, k=tig+4} @ n=nt*8+g

        #pragma unroll
        for (int mt = 0; mt < 2; mt++)
            #pragma unroll
            for (int nt = 0; nt < 8; nt++) {
                asm volatile(
                    "mma.sync.aligned.m16n8k8.row.col.f32.tf32.tf32.f32 "
                    "{%0,%1,%2,%3}, {%4,%5,%6,%7}, {%8,%9}, {%0,%1,%2,%3};"
                    : "+f"(acc[mt][nt][0]), "+f"(acc[mt][nt][1]),
                      "+f"(acc[mt][nt][2]), "+f"(acc[mt][nt][3])
                    : "r"(A[mt][0]), "r"(A[mt][1]), "r"(A[mt][2]), "r"(A[mt][3]),
                      "r"(Bf[nt].x), "r"(Bf[nt].y));
            }
    }

    // ---- epilogue: +bias, min over all 64 couts fully in-warp, tanh(tanh), store ----
    // acc[mt][nt]: c0=(col g, n=nt*8+2tig) c1=(g, +1) c2=(col g+8, n) c3=(g+8, +1)
    #pragma unroll
    for (int mt = 0; mt < 2; mt++) {
        float v0 = 3.4e38f, v1 = 3.4e38f;
        #pragma unroll
        for (int nt = 0; nt < 8; nt++) {
            const int n0 = nt * 8 + 2 * tig;
            const float b0 = bsh[n0], b1 = bsh[n0 + 1];
            v0 = fminf(v0, fminf(acc[mt][nt][0] + b0, acc[mt][nt][1] + b1));
            v1 = fminf(v1, fminf(acc[mt][nt][2] + b0, acc[mt][nt][3] + b1));
        }
        // fold across tig (lanes xor 1,2 share the same pixel)
        v0 = fminf(v0, __shfl_xor_sync(0xffffffffu, v0, 1));
        v0 = fminf(v0, __shfl_xor_sync(0xffffffffu, v0, 2));
        v1 = fminf(v1, __shfl_xor_sync(0xffffffffu, v1, 1));
        v1 = fminf(v1, __shfl_xor_sync(0xffffffffu, v1, 2));

        if (tig == 0) {
            const int oy = y0 + rbase + mt;
            if (oy < OH) {
                float* orow = out + (size_t)b * (OH * OW) + (size_t)oy * OW;
                const int ox0 = x0 + g;          // <= 247, always valid
                orow[ox0] = tanhf(tanhf(v0));
                if (ox0 + 8 < OW)
                    orow[ox0 + 8] = tanhf(tanhf(v1));
            }
        }
    }
}

extern "C" void kernel_launch(void* const* d_in, const int* in_sizes, int n_in,
                              void* d_out, int out_size) {
    const float* x  = (const float*)d_in[0];
    const float* w  = (const float*)d_in[1];
    const float* bi = (const float*)d_in[2];
    float* out = (float*)d_out;

    prep_weights<<<(COUT * KDIM + 255) / 256, 256>>>(w);

    const int smem_bytes = S_TOTAL * 4;  // 61,632 B
    cudaFuncSetAttribute(conv_min_tanh_kernel,
                         cudaFuncAttributeMaxDynamicSharedMemorySize, smem_bytes);

    dim3 grid(16, 16, 64);   // 16x16 col/row tiles (256 >= 254), batch 64
    conv_min_tanh_kernel<<<grid, 256, smem_bytes>>>(x, bi, out);
}